// round 17
// baseline (speedup 1.0000x reference)
#include <cuda_runtime.h>
#include <cuda_fp16.h>
#include <cstdint>

#define FULLMASK 0xffffffffu
#define MINV 1e-12f
#define EPSV 1e-6f
#define MAXN (1.0f - 1e-5f)
#define KPI  (1.0f/0.66f)

#define NWARP 28
#define NTHR  (NWARP*32)

// shared layout (float offsets)
#define OFF_W4H   0
#define OFF_FW1H  8192
#define OFF_FW2H  12288
#define OFF_CONST 20480
#define OFF_STAGE 21392
#define WSTRIDE   1056
#define SOFF_ST2  0
#define SOFF_XT   512
#define SOFF_WKM  768
#define SOFF_AARR 784
#define SOFF_MASK 788
#define SOFF_XK   792
#define SOFF_PB   800
#define SMEM_FLOATS (OFF_STAGE + NWARP*WSTRIDE)
#define SMEM_BYTES  (SMEM_FLOATS*4)

typedef unsigned long long u64t;

__device__ float g_const[1024];
// 0 klp[4][64], 256 hb[4][64], 512 fb1h[128], 640 fb2h[128], 768 gb1h[64], 832 gb2h[64], 896 scal[12]

__device__ __forceinline__ float wred(float v){
    v += __shfl_xor_sync(FULLMASK, v, 16);
    v += __shfl_xor_sync(FULLMASK, v, 8);
    v += __shfl_xor_sync(FULLMASK, v, 4);
    v += __shfl_xor_sync(FULLMASK, v, 2);
    v += __shfl_xor_sync(FULLMASK, v, 1);
    return v;
}
__device__ __forceinline__ float tanh_pos(float xx){
    float e = __expf(-2.0f*xx);
    return __fdividef(1.0f - e, 1.0f + e);
}
__device__ __forceinline__ float artanh_c(float xx){
    xx = fminf(fmaxf(xx, -1.0f + EPSV), 1.0f - EPSV);
    return 0.5f*__logf(__fdividef(1.0f + xx, 1.0f - xx));
}
__device__ __forceinline__ u64t dup2(float x){
    u64t r; asm("mov.b64 %0, {%1, %1};" : "=l"(r) : "f"(x)); return r;
}
__device__ __forceinline__ void fma2(u64t& d, u64t a, u64t b){
    asm("fma.rn.f32x2 %0, %1, %2, %0;" : "+l"(d) : "l"(a), "l"(b));
}
__device__ __forceinline__ float2 unp(u64t v){
    float2 r; asm("mov.b64 {%0, %1}, %2;" : "=f"(r.x), "=f"(r.y) : "l"(v)); return r;
}
__device__ __forceinline__ void cpa8(uint32_t saddr, const void* g){
    asm volatile("cp.async.ca.shared.global [%0], [%1], 8;" :: "r"(saddr), "l"(g));
}
#define CP_COMMIT() asm volatile("cp.async.commit_group;")
#define CP_WAIT0()  asm volatile("cp.async.wait_group 0;")

template<int V>
__device__ __forceinline__ void emap(const float* __restrict__ b, float* __restrict__ dst,
                                     float* __restrict__ n2dst, bool doproj){
    int l = threadIdx.x & 31;
    float u[V]; float s = 0.f;
    #pragma unroll
    for (int c=0;c<V;c++){ u[c] = b[V*l+c]; s += u[c]*u[c]; }
    float n2 = wred(s);
    float n  = sqrtf(fmaxf(n2, MINV));
    float f  = __fdividef(tanh_pos(n), n);
    float h2 = f*f*n2;
    if (doproj){
        float pn = sqrtf(fmaxf(h2, MINV));
        if (pn > MAXN){ f *= __fdividef(MAXN, pn); h2 = MAXN*MAXN; }
    }
    #pragma unroll
    for (int c=0;c<V;c++) dst[V*l+c] = f*u[c];
    if (l == 0) *n2dst = h2;
}

__global__ void prep_kernel(const float* __restrict__ kt, const float* __restrict__ lin_b,
                            const float* __restrict__ fb1, const float* __restrict__ fb2,
                            const float* __restrict__ gb1, const float* __restrict__ gb2){
    int w = threadIdx.x >> 5;
    if (w < 4){
        emap<2>(kt + w*64,    g_const + w*64,       g_const + 896 + w, false);
        emap<2>(lin_b + w*64, g_const + 256 + w*64, g_const + 900 + w, true);
    } else if (w == 4) emap<4>(fb1, g_const + 512, g_const + 904, true);
    else if (w == 5)   emap<4>(fb2, g_const + 640, g_const + 905, true);
    else if (w == 6)   emap<2>(gb1, g_const + 768, g_const + 906, true);
    else if (w == 7)   emap<2>(gb2, g_const + 832, g_const + 907, true);
}

// (kept for tail E1/E2 only)
template<int V>
__device__ __forceinline__ void blin_nl(float* h, const float* bvec, float b2,
                                        float ax_in, bool do_act,
                                        float& out_ax, float& out_n2){
    float s = 0.f;
    #pragma unroll
    for (int c=0;c<V;c++) s += h[c]*h[c];
    float mv2 = wred(s);
    float mvn = sqrtf(fmaxf(mv2, MINV));
    float fac = __fdividef(tanh_pos(mvn*ax_in), mvn);
    float f2  = fac*fac*mv2;
    { float pn = sqrtf(fmaxf(f2, MINV));
      if (pn > MAXN){ fac *= __fdividef(MAXN, pn); f2 = MAXN*MAXN; } }
    float mh = 0.f;
    #pragma unroll
    for (int c=0;c<V;c++) mh += h[c]*bvec[c];
    mh = wred(mh);
    float xy  = fac*mh;
    float A   = 1.0f + 2.0f*xy + b2;
    float B   = 1.0f - f2;
    float D   = fmaxf(1.0f + 2.0f*xy + f2*b2, MINV);
    float idn = __fdividef(1.0f, D);
    float r2  = (A*A*f2 + 2.0f*A*B*xy + B*B*b2)*idn*idn;
    float sp  = 1.0f;
    { float rn = sqrtf(fmaxf(r2, MINV));
      if (rn > MAXN){ sp = __fdividef(MAXN, rn); r2 = MAXN*MAXN; } }
    float cA = sp*idn*A*fac, cB = sp*idn*B;
    #pragma unroll
    for (int c=0;c<V;c++) h[c] = cA*h[c] + cB*bvec[c];
    if (do_act){
        float rn = sqrtf(fmaxf(r2, MINV));
        float lm = __fdividef(artanh_c(rn), rn);
        float t = 0.f;
        #pragma unroll
        for (int c=0;c<V;c++){ float u = fmaxf(h[c],0.f)*lm; h[c]=u; t += u*u; }
        float t2 = wred(t);
        float tn = sqrtf(fmaxf(t2, MINV));
        float ef = __fdividef(tanh_pos(tn), tn);
        float o2 = ef*ef*t2;
        float so = 1.0f;
        { float on = sqrtf(fmaxf(o2, MINV));
          if (on > MAXN){ so = __fdividef(MAXN, on); o2 = MAXN*MAXN; } }
        float cc = ef*so;
        #pragma unroll
        for (int c=0;c<V;c++) h[c] *= cc;
        r2 = o2;
    }
    out_n2 = r2;
    float nn = sqrtf(fmaxf(r2, MINV));
    out_ax = __fdividef(artanh_c(nn), nn);
}

__global__ void __launch_bounds__(NTHR, 1)
kp_main(const float* __restrict__ x, const int* __restrict__ nei,
        const float* __restrict__ neimask, const float* __restrict__ lin_w,
        const float* __restrict__ fw1, const float* __restrict__ fw2,
        const float* __restrict__ gw1, const float* __restrict__ gw2,
        float* __restrict__ out, int N)
{
    extern __shared__ float sm[];
    const int tid = threadIdx.x, wid = tid >> 5, l = tid & 31;

    __half* HW  = (__half*)(sm + OFF_W4H);
    __half* HF1 = (__half*)(sm + OFF_FW1H);
    __half* HF2 = (__half*)(sm + OFF_FW2H);

    for (int i = tid; i < 16384; i += NTHR){
        int p = i >> 13, rem = i & 8191, j2 = rem >> 8, q = rem & 255;
        int lane = q >> 3, c8 = q & 7, r01 = c8 >> 2, kk = (c8 >> 1) & 1, oo = c8 & 1;
        int row = 2*j2 + r01, k = 2*p + kk, o = 2*lane + oo;
        HW[i] = __float2half_rn(lin_w[k*4096 + o*64 + row]);
    }
    for (int i = tid; i < 8192; i += NTHR){
        int j2 = i >> 8, q = i & 255, lane = q >> 3, c8 = q & 7, r01 = c8 >> 2, c = c8 & 3;
        int row = 2*j2 + r01, o = 4*lane + c;
        HF1[i] = __float2half_rn(fw1[o*64 + row]);
    }
    for (int i = tid; i < 16384; i += NTHR){
        int j2 = i >> 8, q = i & 255, lane = q >> 3, c8 = q & 7, r01 = c8 >> 2, c = c8 & 3;
        int row = 2*j2 + r01, o = 4*lane + c;
        HF2[i] = __float2half_rn(fw2[o*128 + row]);
    }
    for (int i = tid; i < 908; i += NTHR) sm[OFF_CONST + i] = g_const[i];
    __syncthreads();

    const int node = blockIdx.x*NWARP + wid;
    if (node >= N) return;

    float* S   = sm + OFF_STAGE + wid*WSTRIDE;
    float* ST2 = S + SOFF_ST2;
    float* XT  = S + SOFF_XT;
    float* PB  = S + SOFF_PB;
    const float* KLP  = sm + OFF_CONST;
    const float* HB   = KLP + 256;
    const float* FB1H = KLP + 512;
    const float* FB2H = KLP + 640;
    const float* GB1H = KLP + 768;
    const float* GB2H = KLP + 832;
    const float* SC   = KLP + 896;

    // group-0 neighbor prefetch
    {
        #pragma unroll
        for (int mm=0;mm<4;mm++){
            int idx = __ldg(nei + node*16 + mm);
            uint32_t dst = (uint32_t)__cvta_generic_to_shared(PB + mm*64 + 2*l);
            cpa8(dst, x + (size_t)idx*64 + 2*l);
        }
        CP_COMMIT();
    }

    // center point
    float2 xv = *(const float2*)(x + node*64 + 2*l);
    float x2 = wred(xv.x*xv.x + xv.y*xv.y);
    { float n = sqrtf(fmaxf(x2, MINV));
      if (n > MAXN){ float s = __fdividef(MAXN, n); xv.x*=s; xv.y*=s; x2 = MAXN*MAXN; } }

    {
        float xk[4];
        #pragma unroll
        for (int k=0;k<4;k++){
            float2 kp = *(const float2*)(KLP + k*64 + 2*l);
            xk[k] = wred(xv.x*kp.x + xv.y*kp.y);
        }
        if (l == 0) *(float4*)(S + SOFF_XK) = make_float4(xk[0], xk[1], xk[2], xk[3]);
    }
    __syncwarp();

    float mnum[4] = {0.f,0.f,0.f,0.f};
    float mden = 0.f;

    for (int g = 0; g < 4; g++){
        CP_WAIT0();
        __syncwarp();

        // ---- stage A (row-gathered XT stores: lane l owns rows 2l, 2l+1) ----
        float d_n2 = 0.f, d_xdn = 0.f, d_nk = 0.f;
        float vx[4], vy[4];
        #pragma unroll
        for (int mm=0; mm<4; mm++){
            float2 v = *(const float2*)(PB + mm*64 + 2*l);
            float n2 = wred(v.x*v.x + v.y*v.y);
            float nn = sqrtf(fmaxf(n2, MINV));
            if (nn > MAXN){ float s = __fdividef(MAXN, nn); v.x*=s; v.y*=s; n2 = MAXN*MAXN; }
            vx[mm] = v.x; vy[mm] = v.y;
            float xdn = wred(xv.x*v.x + xv.y*v.y);
            const bool quad = ((l>>2) == mm);
            if (quad){ d_n2 = n2; d_xdn = xdn; }
            #pragma unroll
            for (int k=0;k<4;k++){
                float2 kp = *(const float2*)(KLP + k*64 + 2*l);
                float nk = wred(v.x*kp.x + v.y*kp.y);
                if (quad && (l&3)==k) d_nk = nk;
            }
        }
        *(float4*)(XT + 8*l)     = make_float4(vx[0], vx[1], vx[2], vx[3]);
        *(float4*)(XT + 8*l + 4) = make_float4(vy[0], vy[1], vy[2], vy[3]);
        __syncwarp();
        if (g < 3){
            #pragma unroll
            for (int mm=0;mm<4;mm++){
                int idx = __ldg(nei + node*16 + (g+1)*4 + mm);
                uint32_t dst = (uint32_t)__cvta_generic_to_shared(PB + mm*64 + 2*l);
                cpa8(dst, x + (size_t)idx*64 + 2*l);
            }
            CP_COMMIT();
        }
        {   // lane-parallel chain: lane j = mm*4+k
            const int mmj = (l >> 2) & 3, kj = l & 3;
            float xkj   = S[SOFF_XK + kj];
            float klp2j = SC[kj];
            float a   = 1.0f - 2.0f*d_xdn + d_n2;
            float b   = 1.0f - x2;
            float den = fmaxf(1.0f - 2.0f*d_xdn + x2*d_n2, MINV);
            float idn = __fdividef(1.0f, den);
            float x02 = (a*a*x2 - 2.0f*a*b*d_xdn + b*b*d_n2)*idn*idn;
            float s0  = 1.0f;
            { float n0 = sqrtf(fmaxf(x02, MINV));
              if (n0 > MAXN){ s0 = __fdividef(MAXN, n0); x02 = MAXN*MAXN; } }
            float x0k = (-a*xkj + b*d_nk)*idn*s0;
            float A = 1.0f - 2.0f*x0k + klp2j;
            float B = 1.0f - x02;
            float D = fmaxf(1.0f - 2.0f*x0k + x02*klp2j, MINV);
            float iD = __fdividef(1.0f, D);
            float nsq = (A*A*x02 - 2.0f*A*B*x0k + B*B*klp2j)*iD*iD;
            float nd = sqrtf(fmaxf(nsq, MINV));
            float dd = 2.0f*artanh_c(nd);
            float wv = fmaxf(0.f, 1.0f - dd*KPI);
            float sw = wv + __shfl_xor_sync(FULLMASK, wv, 1);
            sw += __shfl_xor_sync(FULLMASK, sw, 2);
            float isw = __fdividef(1.0f, fmaxf(sw, MINV));
            if (l < 16){
                S[SOFF_WKM + l] = wv*isw;
                if (kj == 0){
                    float nn2 = sqrtf(fmaxf(d_n2, MINV));
                    S[SOFF_AARR + mmj] = __fdividef(artanh_c(nn2), nn2);
                    S[SOFF_MASK + mmj] = __ldg(neimask + node*16 + g*4 + mmj);
                }
            }
        }
        __syncwarp();

        // ---- stage B: two k-pair passes, packed f32x2 matvec ----
        float kn0[4], kn1[4], kdn[4];
        #pragma unroll
        for (int mm=0;mm<4;mm++){ kn0[mm]=0.f; kn1[mm]=0.f; kdn[mm]=0.f; }
        #pragma unroll 1
        for (int p=0;p<2;p++){
            u64t acc2[2][2][2];
            #pragma unroll
            for (int kk=0;kk<2;kk++)
                #pragma unroll
                for (int oo=0;oo<2;oo++)
                    #pragma unroll
                    for (int pr=0;pr<2;pr++) acc2[kk][oo][pr] = 0ull;
            #pragma unroll 2
            for (int j2=0;j2<32;j2++){
                ulonglong2 xe = *(const ulonglong2*)(XT + (2*j2+0)*4);
                ulonglong2 xo = *(const ulonglong2*)(XT + (2*j2+1)*4);
                uint4 w = *(const uint4*)(HW + p*8192 + j2*256 + 8*l);
                {   float2 f0 = __half22float2(*(const __half2*)&w.x);
                    float2 f1 = __half22float2(*(const __half2*)&w.y);
                    u64t w00=dup2(f0.x), w01=dup2(f0.y), w10=dup2(f1.x), w11=dup2(f1.y);
                    fma2(acc2[0][0][0], w00, xe.x); fma2(acc2[0][0][1], w00, xe.y);
                    fma2(acc2[0][1][0], w01, xe.x); fma2(acc2[0][1][1], w01, xe.y);
                    fma2(acc2[1][0][0], w10, xe.x); fma2(acc2[1][0][1], w10, xe.y);
                    fma2(acc2[1][1][0], w11, xe.x); fma2(acc2[1][1][1], w11, xe.y); }
                {   float2 f0 = __half22float2(*(const __half2*)&w.z);
                    float2 f1 = __half22float2(*(const __half2*)&w.w);
                    u64t w00=dup2(f0.x), w01=dup2(f0.y), w10=dup2(f1.x), w11=dup2(f1.y);
                    fma2(acc2[0][0][0], w00, xo.x); fma2(acc2[0][0][1], w00, xo.y);
                    fma2(acc2[0][1][0], w01, xo.x); fma2(acc2[0][1][1], w01, xo.y);
                    fma2(acc2[1][0][0], w10, xo.x); fma2(acc2[1][0][1], w10, xo.y);
                    fma2(acc2[1][1][0], w11, xo.x); fma2(acc2[1][1][1], w11, xo.y); }
            }
            float accf[2][4][2];
            #pragma unroll
            for (int kk=0;kk<2;kk++)
                #pragma unroll
                for (int oo=0;oo<2;oo++)
                    #pragma unroll
                    for (int pr=0;pr<2;pr++){
                        float2 t = unp(acc2[kk][oo][pr]);
                        accf[kk][2*pr+0][oo] = t.x;
                        accf[kk][2*pr+1][oo] = t.y;
                    }
            float2 hbv0 = *(const float2*)(HB + (2*p+0)*64 + 2*l);
            float2 hbv1 = *(const float2*)(HB + (2*p+1)*64 + 2*l);
            float d_mx2 = 0.f, d_mh = 0.f;
            #pragma unroll
            for (int kk=0;kk<2;kk++){
                float2 hbv = kk ? hbv1 : hbv0;
                #pragma unroll
                for (int mm=0;mm<4;mm++){
                    float a0=accf[kk][mm][0], a1=accf[kk][mm][1];
                    float mx2 = wred(a0*a0 + a1*a1);
                    float mh  = wred(a0*hbv.x + a1*hbv.y);
                    if (l == kk*4+mm){ d_mx2 = mx2; d_mh = mh; }
                }
            }
            float c1, c2, cwv;
            {
                const int kkj = (l >> 2) & 1, mmj = l & 3;
                const int kj = 2*p + kkj;
                float aa   = S[SOFF_AARR + mmj];
                float hb2k = SC[4 + kj];
                float wkmv = S[SOFF_WKM + mmj*4 + kj];
                float mxn = sqrtf(fmaxf(d_mx2, MINV));
                float fac = __fdividef(tanh_pos(mxn*aa), mxn);
                float f2  = fac*fac*d_mx2;
                { float pn = sqrtf(fmaxf(f2, MINV));
                  if (pn > MAXN){ fac *= __fdividef(MAXN, pn); f2 = MAXN*MAXN; } }
                float xy = fac*d_mh;
                float A = 1.0f + 2.0f*xy + hb2k;
                float B = 1.0f - f2;
                float D = fmaxf(1.0f + 2.0f*xy + f2*hb2k, MINV);
                float iD = __fdividef(1.0f, D);
                float r2 = (A*A*f2 + 2.0f*A*B*xy + B*B*hb2k)*iD*iD;
                float sp = 1.0f;
                { float rn = sqrtf(fmaxf(r2, MINV));
                  if (rn > MAXN){ sp = __fdividef(MAXN, rn); r2 = MAXN*MAXN; } }
                float fk  = __fdividef(2.0f, 1.0f + r2);
                float kk2 = fk*fk*r2;
                float lor = rsqrtf(fmaxf(1.0f - kk2, MINV));
                cwv = wkmv*lor;
                float cf  = cwv*fk*sp*iD;
                c1 = cf*A*fac;
                c2 = cf*B;
            }
            #pragma unroll
            for (int kk=0;kk<2;kk++){
                float2 hbv = kk ? hbv1 : hbv0;
                #pragma unroll
                for (int mm=0;mm<4;mm++){
                    const int j = kk*4+mm;
                    float c1j = __shfl_sync(FULLMASK, c1, j);
                    float c2j = __shfl_sync(FULLMASK, c2, j);
                    float cwj = __shfl_sync(FULLMASK, cwv, j);
                    kn0[mm] += c1j*accf[kk][mm][0] + c2j*hbv.x;
                    kn1[mm] += c1j*accf[kk][mm][1] + c2j*hbv.y;
                    kdn[mm] += cwj;
                }
            }
        }
        __syncwarp();

        // ---- stage C: lane-parallel Klein normalize; row-gathered XT stores ----
        float d_q2 = 0.f, d_kdn = 0.f;
        #pragma unroll
        for (int mm=0;mm<4;mm++){
            float q2 = wred(kn0[mm]*kn0[mm] + kn1[mm]*kn1[mm]);
            if (l == mm){ d_q2 = q2; d_kdn = kdn[mm]; }
        }
        float d_axC, cscv;
        {
            float ikd = __fdividef(1.0f, fmaxf(d_kdn, MINV));
            float kk2 = ikd*ikd*d_q2;
            float s2 = __fdividef(1.0f, 1.0f + sqrtf(fmaxf(1.0f - kk2, MINV)));
            float p2 = s2*s2*kk2;
            float spp = 1.0f;
            { float pn = sqrtf(fmaxf(p2, MINV));
              if (pn > MAXN){ spp = __fdividef(MAXN, pn); p2 = MAXN*MAXN; } }
            cscv = s2*spp*ikd;
            float nn = sqrtf(fmaxf(p2, MINV));
            d_axC = __fdividef(artanh_c(nn), nn);
        }
        {
            float cj0 = __shfl_sync(FULLMASK, cscv, 0);
            float cj1 = __shfl_sync(FULLMASK, cscv, 1);
            float cj2 = __shfl_sync(FULLMASK, cscv, 2);
            float cj3 = __shfl_sync(FULLMASK, cscv, 3);
            *(float4*)(XT + 8*l)     = make_float4(cj0*kn0[0], cj1*kn0[1], cj2*kn0[2], cj3*kn0[3]);
            *(float4*)(XT + 8*l + 4) = make_float4(cj0*kn1[0], cj1*kn1[1], cj2*kn1[2], cj3*kn1[3]);
        }
        __syncwarp();

        // ---- stage D1: packed matvec ----
        u64t h1p[4][2];
        #pragma unroll
        for (int c=0;c<4;c++){ h1p[c][0]=0ull; h1p[c][1]=0ull; }
        #pragma unroll 2
        for (int j2=0;j2<32;j2++){
            ulonglong2 xe = *(const ulonglong2*)(XT + (2*j2+0)*4);
            ulonglong2 xo = *(const ulonglong2*)(XT + (2*j2+1)*4);
            uint4 w = *(const uint4*)(HF1 + j2*256 + 8*l);
            {   float2 f0 = __half22float2(*(const __half2*)&w.x);
                float2 f1 = __half22float2(*(const __half2*)&w.y);
                u64t wc0=dup2(f0.x), wc1=dup2(f0.y), wc2=dup2(f1.x), wc3=dup2(f1.y);
                fma2(h1p[0][0], wc0, xe.x); fma2(h1p[0][1], wc0, xe.y);
                fma2(h1p[1][0], wc1, xe.x); fma2(h1p[1][1], wc1, xe.y);
                fma2(h1p[2][0], wc2, xe.x); fma2(h1p[2][1], wc2, xe.y);
                fma2(h1p[3][0], wc3, xe.x); fma2(h1p[3][1], wc3, xe.y); }
            {   float2 f0 = __half22float2(*(const __half2*)&w.z);
                float2 f1 = __half22float2(*(const __half2*)&w.w);
                u64t wc0=dup2(f0.x), wc1=dup2(f0.y), wc2=dup2(f1.x), wc3=dup2(f1.y);
                fma2(h1p[0][0], wc0, xo.x); fma2(h1p[0][1], wc0, xo.y);
                fma2(h1p[1][0], wc1, xo.x); fma2(h1p[1][1], wc1, xo.y);
                fma2(h1p[2][0], wc2, xo.x); fma2(h1p[2][1], wc2, xo.y);
                fma2(h1p[3][0], wc3, xo.x); fma2(h1p[3][1], wc3, xo.y); }
        }
        float h1[4][4];
        #pragma unroll
        for (int c=0;c<4;c++)
            #pragma unroll
            for (int pr=0;pr<2;pr++){
                float2 t = unp(h1p[c][pr]);
                h1[2*pr+0][c] = t.x;
                h1[2*pr+1][c] = t.y;
            }
        __syncwarp();

        // ---- D1 epilogue: lane-parallel blinear(act) ----
        float bv1[4] = {FB1H[4*l], FB1H[4*l+1], FB1H[4*l+2], FB1H[4*l+3]};
        float d_mv2 = 0.f, d_mh1 = 0.f;
        #pragma unroll
        for (int mm=0;mm<4;mm++){
            float s=0.f, mh=0.f;
            #pragma unroll
            for (int c=0;c<4;c++){ s += h1[mm][c]*h1[mm][c]; mh += h1[mm][c]*bv1[c]; }
            s = wred(s); mh = wred(mh);
            if (l == mm){ d_mv2 = s; d_mh1 = mh; }
        }
        float cA1, cB1, lm1;
        {
            const float b2 = SC[8];
            float mvn = sqrtf(fmaxf(d_mv2, MINV));
            float fac = __fdividef(tanh_pos(mvn*d_axC), mvn);
            float f2 = fac*fac*d_mv2;
            { float pn = sqrtf(fmaxf(f2, MINV));
              if (pn > MAXN){ fac *= __fdividef(MAXN, pn); f2 = MAXN*MAXN; } }
            float xy = fac*d_mh1;
            float A = 1.0f + 2.0f*xy + b2;
            float B = 1.0f - f2;
            float D = fmaxf(1.0f + 2.0f*xy + f2*b2, MINV);
            float iD = __fdividef(1.0f, D);
            float r2 = (A*A*f2 + 2.0f*A*B*xy + B*B*b2)*iD*iD;
            float sp = 1.0f;
            { float rn = sqrtf(fmaxf(r2, MINV));
              if (rn > MAXN){ sp = __fdividef(MAXN, rn); r2 = MAXN*MAXN; } }
            cA1 = sp*iD*A*fac; cB1 = sp*iD*B;
            float rn = sqrtf(fmaxf(r2, MINV));
            lm1 = __fdividef(artanh_c(rn), rn);
        }
        float d_t2 = 0.f;
        #pragma unroll
        for (int mm=0;mm<4;mm++){
            float cAj = __shfl_sync(FULLMASK, cA1, mm);
            float cBj = __shfl_sync(FULLMASK, cB1, mm);
            float lmj = __shfl_sync(FULLMASK, lm1, mm);
            float t = 0.f;
            #pragma unroll
            for (int c=0;c<4;c++){
                float u = fmaxf(cAj*h1[mm][c] + cBj*bv1[c], 0.f)*lmj;
                h1[mm][c] = u; t += u*u;
            }
            t = wred(t);
            if (l == mm) d_t2 = t;
        }
        float cc1, d_ax1;
        {
            float tn = sqrtf(fmaxf(d_t2, MINV));
            float ef = __fdividef(tanh_pos(tn), tn);
            float o2 = ef*ef*d_t2;
            float so = 1.0f;
            { float on = sqrtf(fmaxf(o2, MINV));
              if (on > MAXN){ so = __fdividef(MAXN, on); o2 = MAXN*MAXN; } }
            cc1 = ef*so;
            float nn = sqrtf(fmaxf(o2, MINV));
            d_ax1 = __fdividef(artanh_c(nn), nn);
        }
        #pragma unroll
        for (int mm=0;mm<4;mm++){
            float ccj = __shfl_sync(FULLMASK, cc1, mm);
            #pragma unroll
            for (int c=0;c<4;c++) h1[mm][c] *= ccj;
        }
        // rotated row stores: rows 4l..4l+3 owned by lane l; rotation avoids l±2 conflicts
        #pragma unroll
        for (int i=0;i<4;i++){
            int c = (l + i) & 3;
            *(float4*)(ST2 + (4*l + c)*4) = make_float4(h1[0][c], h1[1][c], h1[2][c], h1[3][c]);
        }
        __syncwarp();

        // ---- stage D2: packed matvec ----
        u64t h2p[4][2];
        #pragma unroll
        for (int c=0;c<4;c++){ h2p[c][0]=0ull; h2p[c][1]=0ull; }
        #pragma unroll 2
        for (int j2=0;j2<64;j2++){
            ulonglong2 xe = *(const ulonglong2*)(ST2 + (2*j2+0)*4);
            ulonglong2 xo = *(const ulonglong2*)(ST2 + (2*j2+1)*4);
            uint4 w = *(const uint4*)(HF2 + j2*256 + 8*l);
            {   float2 f0 = __half22float2(*(const __half2*)&w.x);
                float2 f1 = __half22float2(*(const __half2*)&w.y);
                u64t wc0=dup2(f0.x), wc1=dup2(f0.y), wc2=dup2(f1.x), wc3=dup2(f1.y);
                fma2(h2p[0][0], wc0, xe.x); fma2(h2p[0][1], wc0, xe.y);
                fma2(h2p[1][0], wc1, xe.x); fma2(h2p[1][1], wc1, xe.y);
                fma2(h2p[2][0], wc2, xe.x); fma2(h2p[2][1], wc2, xe.y);
                fma2(h2p[3][0], wc3, xe.x); fma2(h2p[3][1], wc3, xe.y); }
            {   float2 f0 = __half22float2(*(const __half2*)&w.z);
                float2 f1 = __half22float2(*(const __half2*)&w.w);
                u64t wc0=dup2(f0.x), wc1=dup2(f0.y), wc2=dup2(f1.x), wc3=dup2(f1.y);
                fma2(h2p[0][0], wc0, xo.x); fma2(h2p[0][1], wc0, xo.y);
                fma2(h2p[1][0], wc1, xo.x); fma2(h2p[1][1], wc1, xo.y);
                fma2(h2p[2][0], wc2, xo.x); fma2(h2p[2][1], wc2, xo.y);
                fma2(h2p[3][0], wc3, xo.x); fma2(h2p[3][1], wc3, xo.y); }
        }
        float h2a[4][4];
        #pragma unroll
        for (int c=0;c<4;c++)
            #pragma unroll
            for (int pr=0;pr<2;pr++){
                float2 t = unp(h2p[c][pr]);
                h2a[2*pr+0][c] = t.x;
                h2a[2*pr+1][c] = t.y;
            }

        // ---- D2 epilogue: lane-parallel blinear + Klein accumulation ----
        float bv2[4] = {FB2H[4*l], FB2H[4*l+1], FB2H[4*l+2], FB2H[4*l+3]};
        float d2_mv2 = 0.f, d2_mh = 0.f;
        #pragma unroll
        for (int mm=0;mm<4;mm++){
            float s=0.f, mh=0.f;
            #pragma unroll
            for (int c=0;c<4;c++){ s += h2a[mm][c]*h2a[mm][c]; mh += h2a[mm][c]*bv2[c]; }
            s = wred(s); mh = wred(mh);
            if (l == mm){ d2_mv2 = s; d2_mh = mh; }
        }
        float e1v, e2v, cwv2;
        {
            const float b2 = SC[9];
            float mvn = sqrtf(fmaxf(d2_mv2, MINV));
            float fac = __fdividef(tanh_pos(mvn*d_ax1), mvn);
            float f2 = fac*fac*d2_mv2;
            { float pn = sqrtf(fmaxf(f2, MINV));
              if (pn > MAXN){ fac *= __fdividef(MAXN, pn); f2 = MAXN*MAXN; } }
            float xy = fac*d2_mh;
            float A = 1.0f + 2.0f*xy + b2;
            float B = 1.0f - f2;
            float D = fmaxf(1.0f + 2.0f*xy + f2*b2, MINV);
            float iD = __fdividef(1.0f, D);
            float r2 = (A*A*f2 + 2.0f*A*B*xy + B*B*b2)*iD*iD;
            float sp = 1.0f;
            { float rn = sqrtf(fmaxf(r2, MINV));
              if (rn > MAXN){ sp = __fdividef(MAXN, rn); r2 = MAXN*MAXN; } }
            float cA = sp*iD*A*fac, cB = sp*iD*B;
            float fk = __fdividef(2.0f, 1.0f + r2);
            float kk2v = fk*fk*r2;
            float lor = rsqrtf(fmaxf(1.0f - kk2v, MINV));
            float msk = S[SOFF_MASK + (l & 3)];
            cwv2 = msk*lor;
            float cf = cwv2*fk;
            e1v = cf*cA; e2v = cf*cB;
        }
        #pragma unroll
        for (int mm=0;mm<4;mm++){
            float e1j = __shfl_sync(FULLMASK, e1v, mm);
            float e2j = __shfl_sync(FULLMASK, e2v, mm);
            float cwj = __shfl_sync(FULLMASK, cwv2, mm);
            mden += cwj;
            #pragma unroll
            for (int c=0;c<4;c++) mnum[c] += e1j*h2a[mm][c] + e2j*bv2[c];
        }
        __syncwarp();
    }

    // ---- neighbor Klein midpoint -> mid (128-d) ----
    float imd = __fdividef(1.0f, fmaxf(mden, MINV));
    float mk4[4]; float s = 0.f;
    #pragma unroll
    for (int c=0;c<4;c++){ mk4[c] = mnum[c]*imd; s += mk4[c]*mk4[c]; }
    float kk2 = wred(s);
    float s2 = __fdividef(1.0f, 1.0f + sqrtf(fmaxf(1.0f - kk2, MINV)));
    float p2 = s2*s2*kk2;
    float spp = 1.0f;
    { float pn = sqrtf(fmaxf(p2, MINV));
      if (pn > MAXN){ spp = __fdividef(MAXN, pn); p2 = MAXN*MAXN; } }
    float cc = s2*spp;
    #pragma unroll
    for (int c=0;c<4;c++) mk4[c] *= cc;
    *(float4*)(ST2 + 4*l) = make_float4(mk4[0], mk4[1], mk4[2], mk4[3]);
    float axmid;
    { float nn = sqrtf(fmaxf(p2, MINV)); axmid = __fdividef(artanh_c(nn), nn); }
    __syncwarp();

    // ---- tail E1 ----
    float g1v[2] = {0.f, 0.f};
    #pragma unroll 4
    for (int i4=0;i4<32;i4++){
        float4 xs = *(const float4*)(ST2 + i4*4);
        float4 w0 = __ldg((const float4*)(gw1 + (2*l)*128 + i4*4));
        float4 w1 = __ldg((const float4*)(gw1 + (2*l+1)*128 + i4*4));
        g1v[0] += w0.x*xs.x + w0.y*xs.y + w0.z*xs.z + w0.w*xs.w;
        g1v[1] += w1.x*xs.x + w1.y*xs.y + w1.z*xs.z + w1.w*xs.w;
    }
    __syncwarp();
    float axo1, r2o1;
    {
        float bvg1[2] = {GB1H[2*l], GB1H[2*l+1]};
        blin_nl<2>(g1v, bvg1, SC[10], axmid, true, axo1, r2o1);
    }
    *(float2*)(ST2 + 2*l) = make_float2(g1v[0], g1v[1]);
    __syncwarp();

    // ---- tail E2 ----
    float g2v[2] = {0.f, 0.f};
    #pragma unroll 4
    for (int i4=0;i4<16;i4++){
        float4 xs = *(const float4*)(ST2 + i4*4);
        float4 w0 = __ldg((const float4*)(gw2 + (2*l)*64 + i4*4));
        float4 w1 = __ldg((const float4*)(gw2 + (2*l+1)*64 + i4*4));
        g2v[0] += w0.x*xs.x + w0.y*xs.y + w0.z*xs.z + w0.w*xs.w;
        g2v[1] += w1.x*xs.x + w1.y*xs.y + w1.z*xs.z + w1.w*xs.w;
    }
    float axo2, r2o2;
    {
        float bvg2[2] = {GB2H[2*l], GB2H[2*l+1]};
        blin_nl<2>(g2v, bvg2, SC[11], axo1, false, axo2, r2o2);
    }
    *(float2*)(out + node*64 + 2*l) = make_float2(g2v[0], g2v[1]);
}

extern "C" void kernel_launch(void* const* d_in, const int* in_sizes, int n_in,
                              void* d_out, int out_size){
    const float* x       = (const float*)d_in[0];
    const int*   nei     = (const int*)  d_in[1];
    const float* neimask = (const float*)d_in[2];
    const float* kt      = (const float*)d_in[3];
    const float* lin_w   = (const float*)d_in[4];
    const float* lin_b   = (const float*)d_in[5];
    const float* fw1     = (const float*)d_in[6];
    const float* fb1     = (const float*)d_in[7];
    const float* fw2     = (const float*)d_in[8];
    const float* fb2     = (const float*)d_in[9];
    const float* gw1     = (const float*)d_in[10];
    const float* gb1     = (const float*)d_in[11];
    const float* gw2     = (const float*)d_in[12];
    const float* gb2     = (const float*)d_in[13];
    float* out = (float*)d_out;
    const int N = in_sizes[0]/64;

    cudaFuncSetAttribute(kp_main, cudaFuncAttributeMaxDynamicSharedMemorySize, SMEM_BYTES);
    prep_kernel<<<1, 256>>>(kt, lin_b, fb1, fb2, gb1, gb2);
    kp_main<<<(N + NWARP - 1)/NWARP, NTHR, SMEM_BYTES>>>(x, nei, neimask, lin_w, fw1, fw2, gw1, gw2, out, N);
}